// round 4
// baseline (speedup 1.0000x reference)
#include <cuda_runtime.h>

// FMFMNeuronInhib: T=1024 LIF steps over B=16384 neurons. HBM stream.
// R4: 8 balanced chunks. Recurrence forgets at x0.9/step, so each chunk
// re-derives state with 192 discarded warm-up steps (0.9^192 ~ 1.6e-9).
// Balance: chunk 0 stores 296 steps (no warm-up); chunks 1-7 do 192 warm
// + 104 stored = 296 steps each -> every block runs the identical step
// count (R3's critical path was 448). 1024 blocks / 4096 warps; U=4
// depth-2 register prefetch (16 loads/thread in flight, 16MB chip-wide).
// Warm-up re-reads hit L2 (trailing chunk re-reads within a ~109MB window);
// streaming stores keep the 128MB output from evicting it.

#define T_STEPS 1024
#define BATCH   16384
#define NCHUNK  8
#define WARM    192
#define L_TAIL  104                      // stored steps, chunks 1..7
#define L_HEAD  (T_STEPS - (NCHUNK - 1) * L_TAIL)  // 296, chunk 0
#define U       4
#define TPB     128
#define STRIDE  ((size_t)BATCH)

template <bool STORE, bool PREFETCH>
__device__ __forceinline__ void win(
    float2* __restrict__ buf,        // consumed; refilled from `pre` if PREFETCH
    const float2* __restrict__ pre,  // absolute src of window t+2U
    float& mem, float& inh,
    float w0, float w1, float wi,
    float* __restrict__ spk, float* __restrict__ memo, int tbase)
{
#pragma unroll
    for (int u = 0; u < U; u++) {
        const float2 v = buf[u];
        if (PREFETCH)
            buf[u] = __ldg(pre + (size_t)u * STRIDE);  // keep depth-2 in flight

        // inh = 0.6*inh + x0
        inh = fmaf(0.6f, inh, v.x);
        // cur = 0.7*x0 + 1.0*x1 + w_inh*inh
        float cur = fmaf(w0, v.x, w1 * v.y);
        cur = fmaf(wi, inh, cur);
        // reset from OLD mem (threshold 1), then mem = 0.9*mem + cur - reset
        const float reset = (mem > 1.0f) ? 1.0f : 0.0f;
        mem = fmaf(0.9f, mem, cur - reset);

        if (STORE) {
            const float s = (mem > 1.0f) ? 1.0f : 0.0f;
            __stcs(spk  + (size_t)(tbase + u) * STRIDE, s);
            __stcs(memo + (size_t)(tbase + u) * STRIDE, mem);
        }
    }
}

__global__ void __launch_bounds__(TPB, 1) fmfm_kernel(
    const float2* __restrict__ x,      // [T, B] pairs (x0, x1)
    const float*  __restrict__ w_exc,  // [2] = {0.7, 1.0}
    const float*  __restrict__ w_inh,  // [1] = {-1.0}
    float*        __restrict__ out)    // [2, T, B]: spk_rec then mem_rec
{
    const int nb    = BATCH / TPB;                 // blocks per chunk
    const int chunk = blockIdx.x / nb;
    const int b     = (blockIdx.x % nb) * TPB + threadIdx.x;

    const float w0 = __ldg(&w_exc[0]);
    const float w1 = __ldg(&w_exc[1]);
    const float wi = __ldg(&w_inh[0]);

    // Chunk 0: store [0, L_HEAD), no warm-up.
    // Chunk i>=1: store [L_HEAD + (i-1)*L_TAIL, +L_TAIL), warm-up WARM steps.
    const int cs = (chunk == 0) ? 0 : L_HEAD + (chunk - 1) * L_TAIL;
    const int ce = (chunk == 0) ? L_HEAD : cs + L_TAIL;
    const int t0 = (chunk == 0) ? 0 : cs - WARM;   // every block: 296 steps

    const float2* xb   = x + b;
    float*        spk  = out + b;
    float*        memo = out + (size_t)T_STEPS * BATCH + b;

    float mem = 0.0f;
    float inh = 0.0f;

    // Prologue: prefetch windows t0 and t0+U.
    float2 buf0[U], buf1[U];
#pragma unroll
    for (int u = 0; u < U; u++)
        buf0[u] = __ldg(xb + (size_t)(t0 + u) * STRIDE);
#pragma unroll
    for (int u = 0; u < U; u++)
        buf1[u] = __ldg(xb + (size_t)(t0 + U + u) * STRIDE);

    int t = t0;
    // Warm-up: advance state, no stores (empty for chunk 0). WARM % (2U) == 0.
    for (; t < cs; t += 2 * U) {
        win<false, true>(buf0, xb + (size_t)(t + 2 * U) * STRIDE,
                         mem, inh, w0, w1, wi, spk, memo, t);
        win<false, true>(buf1, xb + (size_t)(t + 3 * U) * STRIDE,
                         mem, inh, w0, w1, wi, spk, memo, t + U);
    }
    // Main: store outputs, keep prefetching while data remains.
    for (; t < ce - 2 * U; t += 2 * U) {
        win<true, true>(buf0, xb + (size_t)(t + 2 * U) * STRIDE,
                        mem, inh, w0, w1, wi, spk, memo, t);
        win<true, true>(buf1, xb + (size_t)(t + 3 * U) * STRIDE,
                        mem, inh, w0, w1, wi, spk, memo, t + U);
    }
    // Epilogue: last two windows.
    win<true, false>(buf0, nullptr, mem, inh, w0, w1, wi, spk, memo, t);
    win<true, false>(buf1, nullptr, mem, inh, w0, w1, wi, spk, memo, t + U);
}

extern "C" void kernel_launch(void* const* d_in, const int* in_sizes, int n_in,
                              void* d_out, int out_size) {
    const float* x     = (const float*)d_in[0];  // spike_seq [1024,16384,2]
    const float* w_exc = (const float*)d_in[1];  // [1,2]
    const float* w_inh = (const float*)d_in[2];  // scalar
    float* out = (float*)d_out;                  // [2,1024,16384]

    fmfm_kernel<<<(BATCH / TPB) * NCHUNK, TPB>>>((const float2*)x, w_exc, w_inh, out);
}

// round 5
// speedup vs baseline: 1.2575x; 1.2575x over previous
#include <cuda_runtime.h>

// FMFMNeuronInhib: T=1024 LIF steps over B=16384 neurons. HBM stream.
// R5: R3's geometry (4 chunks, WARM=192 -> warm-up re-reads proven to hit
// L2, only +8MB DRAM) with balanced step counts: chunk 0 stores 400 steps,
// chunks 1-3 do 192 warm + 208 stored = 400 steps each. R3's critical path
// was 448 with chunk-0 blocks idling at 57%; now all 512 blocks run exactly
// 400 steps. R4 (8 chunks) showed that doubling warm-up volume blows the
// L2 reuse window (+110MB DRAM traffic) -- do not add chunks.

#define T_STEPS 1024
#define BATCH   16384
#define NCHUNK  4
#define WARM    192
#define L_TAIL  208                                  // stored, chunks 1..3
#define L_HEAD  (T_STEPS - (NCHUNK - 1) * L_TAIL)    // 400, chunk 0
#define U       8
#define TPB     128
#define STRIDE  ((size_t)BATCH)

template <bool STORE, bool PREFETCH>
__device__ __forceinline__ void win(
    float2* __restrict__ buf,        // consumed; refilled from `pre` if PREFETCH
    const float2* __restrict__ pre,  // absolute src of window t+2U
    float& mem, float& inh,
    float w0, float w1, float wi,
    float* __restrict__ spk, float* __restrict__ memo, int tbase)
{
#pragma unroll
    for (int u = 0; u < U; u++) {
        const float2 v = buf[u];
        if (PREFETCH)
            buf[u] = __ldg(pre + (size_t)u * STRIDE);  // keep depth-2 in flight

        // inh = 0.6*inh + x0
        inh = fmaf(0.6f, inh, v.x);
        // cur = 0.7*x0 + 1.0*x1 + w_inh*inh
        float cur = fmaf(w0, v.x, w1 * v.y);
        cur = fmaf(wi, inh, cur);
        // reset from OLD mem (threshold 1), then mem = 0.9*mem + cur - reset
        const float reset = (mem > 1.0f) ? 1.0f : 0.0f;
        mem = fmaf(0.9f, mem, cur - reset);

        if (STORE) {
            const float s = (mem > 1.0f) ? 1.0f : 0.0f;
            __stcs(spk  + (size_t)(tbase + u) * STRIDE, s);
            __stcs(memo + (size_t)(tbase + u) * STRIDE, mem);
        }
    }
}

__global__ void __launch_bounds__(TPB, 1) fmfm_kernel(
    const float2* __restrict__ x,      // [T, B] pairs (x0, x1)
    const float*  __restrict__ w_exc,  // [2] = {0.7, 1.0}
    const float*  __restrict__ w_inh,  // [1] = {-1.0}
    float*        __restrict__ out)    // [2, T, B]: spk_rec then mem_rec
{
    const int nb    = BATCH / TPB;                 // blocks per chunk
    const int chunk = blockIdx.x / nb;
    const int b     = (blockIdx.x % nb) * TPB + threadIdx.x;

    const float w0 = __ldg(&w_exc[0]);
    const float w1 = __ldg(&w_exc[1]);
    const float wi = __ldg(&w_inh[0]);

    // Chunk 0: store [0, 400), no warm-up (400 steps total).
    // Chunk i>=1: store [400 + (i-1)*208, +208), warm-up 192 (400 steps total).
    const int cs = (chunk == 0) ? 0 : L_HEAD + (chunk - 1) * L_TAIL;
    const int ce = (chunk == 0) ? L_HEAD : cs + L_TAIL;
    const int t0 = (chunk == 0) ? 0 : cs - WARM;

    const float2* xb   = x + b;
    float*        spk  = out + b;
    float*        memo = out + (size_t)T_STEPS * BATCH + b;

    float mem = 0.0f;
    float inh = 0.0f;

    // Prologue: prefetch windows t0 and t0+U.
    float2 buf0[U], buf1[U];
#pragma unroll
    for (int u = 0; u < U; u++)
        buf0[u] = __ldg(xb + (size_t)(t0 + u) * STRIDE);
#pragma unroll
    for (int u = 0; u < U; u++)
        buf1[u] = __ldg(xb + (size_t)(t0 + U + u) * STRIDE);

    int t = t0;
    // Warm-up: advance state, no stores (empty for chunk 0). WARM % 16 == 0.
    for (; t < cs; t += 2 * U) {
        win<false, true>(buf0, xb + (size_t)(t + 2 * U) * STRIDE,
                         mem, inh, w0, w1, wi, spk, memo, t);
        win<false, true>(buf1, xb + (size_t)(t + 3 * U) * STRIDE,
                         mem, inh, w0, w1, wi, spk, memo, t + U);
    }
    // Main stored region (L_HEAD/L_TAIL are multiples of 16).
    for (; t < ce - 2 * U; t += 2 * U) {
        win<true, true>(buf0, xb + (size_t)(t + 2 * U) * STRIDE,
                        mem, inh, w0, w1, wi, spk, memo, t);
        win<true, true>(buf1, xb + (size_t)(t + 3 * U) * STRIDE,
                        mem, inh, w0, w1, wi, spk, memo, t + U);
    }
    // Epilogue: last two windows.
    win<true, false>(buf0, nullptr, mem, inh, w0, w1, wi, spk, memo, t);
    win<true, false>(buf1, nullptr, mem, inh, w0, w1, wi, spk, memo, t + U);
}

extern "C" void kernel_launch(void* const* d_in, const int* in_sizes, int n_in,
                              void* d_out, int out_size) {
    const float* x     = (const float*)d_in[0];  // spike_seq [1024,16384,2]
    const float* w_exc = (const float*)d_in[1];  // [1,2]
    const float* w_inh = (const float*)d_in[2];  // scalar
    float* out = (float*)d_out;                  // [2,1024,16384]

    fmfm_kernel<<<(BATCH / TPB) * NCHUNK, TPB>>>((const float2*)x, w_exc, w_inh, out);
}

// round 7
// speedup vs baseline: 1.3061x; 1.0387x over previous
#include <cuda_runtime.h>

// FMFMNeuronInhib: T=1024 LIF steps over B=16384 neurons. HBM stream.
// R7: R5 geometry (4 balanced chunks, WARM=192, 400 steps/block) + L2
// cache-policy separation, now via the createpolicy/cache_hint path
// (sm_103a ptxas only allows the direct .L2::evict_last qualifier on
// 256-bit loads).
//   - warm-up loads: ld.global.nc.L2::cache_hint (evict_last policy) —
//     first of two readers; pin 75MB warm regions so the trailing chunk's
//     main read hits L2 (R5 measured +34MB DRAM from these misses).
//   - main loads:    __ldcs (evict_first) — always the last reader.
//   - stores:        __stcs (streaming).

#define T_STEPS 1024
#define BATCH   16384
#define NCHUNK  4
#define WARM    192
#define L_TAIL  208                                  // stored, chunks 1..3
#define L_HEAD  (T_STEPS - (NCHUNK - 1) * L_TAIL)    // 400, chunk 0
#define U       8
#define TPB     128
#define STRIDE  ((size_t)BATCH)

// evict_last access policy (covers whole cacheline population, fraction 1.0)
__device__ __forceinline__ unsigned long long make_keep_policy() {
    unsigned long long pol;
    asm("createpolicy.fractional.L2::evict_last.b64 %0, 1.0;" : "=l"(pol));
    return pol;
}

// First-of-two-readers load: keep in L2 until the trailing reader arrives.
__device__ __forceinline__ float2 ldg_keep(const float2* p, unsigned long long pol) {
    float2 v;
    asm("ld.global.nc.L2::cache_hint.v2.f32 {%0,%1}, [%2], %3;"
        : "=f"(v.x), "=f"(v.y) : "l"(p), "l"(pol));
    return v;
}

template <bool STORE, bool PREFETCH, bool KEEP>
__device__ __forceinline__ void win(
    float2* __restrict__ buf,        // consumed; refilled from `pre` if PREFETCH
    const float2* __restrict__ pre,  // absolute src of window t+2U
    unsigned long long pol,
    float& mem, float& inh,
    float w0, float w1, float wi,
    float* __restrict__ spk, float* __restrict__ memo, int tbase)
{
#pragma unroll
    for (int u = 0; u < U; u++) {
        const float2 v = buf[u];
        if (PREFETCH)
            buf[u] = KEEP ? ldg_keep(pre + (size_t)u * STRIDE, pol)
                          : __ldcs(pre + (size_t)u * STRIDE);

        // inh = 0.6*inh + x0
        inh = fmaf(0.6f, inh, v.x);
        // cur = 0.7*x0 + 1.0*x1 + w_inh*inh
        float cur = fmaf(w0, v.x, w1 * v.y);
        cur = fmaf(wi, inh, cur);
        // reset from OLD mem (threshold 1), then mem = 0.9*mem + cur - reset
        const float reset = (mem > 1.0f) ? 1.0f : 0.0f;
        mem = fmaf(0.9f, mem, cur - reset);

        if (STORE) {
            const float s = (mem > 1.0f) ? 1.0f : 0.0f;
            __stcs(spk  + (size_t)(tbase + u) * STRIDE, s);
            __stcs(memo + (size_t)(tbase + u) * STRIDE, mem);
        }
    }
}

__global__ void __launch_bounds__(TPB, 1) fmfm_kernel(
    const float2* __restrict__ x,      // [T, B] pairs (x0, x1)
    const float*  __restrict__ w_exc,  // [2] = {0.7, 1.0}
    const float*  __restrict__ w_inh,  // [1] = {-1.0}
    float*        __restrict__ out)    // [2, T, B]: spk_rec then mem_rec
{
    const int nb    = BATCH / TPB;                 // blocks per chunk
    const int chunk = blockIdx.x / nb;
    const int b     = (blockIdx.x % nb) * TPB + threadIdx.x;

    const float w0 = __ldg(&w_exc[0]);
    const float w1 = __ldg(&w_exc[1]);
    const float wi = __ldg(&w_inh[0]);

    const unsigned long long pol = make_keep_policy();

    // Chunk 0: store [0, 400), no warm-up (400 steps total).
    // Chunk i>=1: store [400 + (i-1)*208, +208), warm-up 192 (400 steps total).
    const int cs = (chunk == 0) ? 0 : L_HEAD + (chunk - 1) * L_TAIL;
    const int ce = (chunk == 0) ? L_HEAD : cs + L_TAIL;
    const int t0 = (chunk == 0) ? 0 : cs - WARM;

    const float2* xb   = x + b;
    float*        spk  = out + b;
    float*        memo = out + (size_t)T_STEPS * BATCH + b;

    float mem = 0.0f;
    float inh = 0.0f;

    // Prologue: prefetch windows t0 and t0+U.
    // Chunks >=1 start in their warm region -> evict_last; chunk 0 -> streaming.
    float2 buf0[U], buf1[U];
    if (chunk == 0) {
#pragma unroll
        for (int u = 0; u < U; u++)
            buf0[u] = __ldcs(xb + (size_t)(t0 + u) * STRIDE);
#pragma unroll
        for (int u = 0; u < U; u++)
            buf1[u] = __ldcs(xb + (size_t)(t0 + U + u) * STRIDE);
    } else {
#pragma unroll
        for (int u = 0; u < U; u++)
            buf0[u] = ldg_keep(xb + (size_t)(t0 + u) * STRIDE, pol);
#pragma unroll
        for (int u = 0; u < U; u++)
            buf1[u] = ldg_keep(xb + (size_t)(t0 + U + u) * STRIDE, pol);
    }

    int t = t0;
    // Warm-up: advance state, no stores, evict_last loads (first reader of
    // data the trailing chunk's main loop will re-read). Empty for chunk 0.
    for (; t < cs; t += 2 * U) {
        win<false, true, true>(buf0, xb + (size_t)(t + 2 * U) * STRIDE, pol,
                               mem, inh, w0, w1, wi, spk, memo, t);
        win<false, true, true>(buf1, xb + (size_t)(t + 3 * U) * STRIDE, pol,
                               mem, inh, w0, w1, wi, spk, memo, t + U);
    }
    // Main stored region: streaming loads (we are the last reader).
    for (; t < ce - 2 * U; t += 2 * U) {
        win<true, true, false>(buf0, xb + (size_t)(t + 2 * U) * STRIDE, pol,
                               mem, inh, w0, w1, wi, spk, memo, t);
        win<true, true, false>(buf1, xb + (size_t)(t + 3 * U) * STRIDE, pol,
                               mem, inh, w0, w1, wi, spk, memo, t + U);
    }
    // Epilogue: last two windows.
    win<true, false, false>(buf0, nullptr, pol, mem, inh, w0, w1, wi, spk, memo, t);
    win<true, false, false>(buf1, nullptr, pol, mem, inh, w0, w1, wi, spk, memo, t + U);
}

extern "C" void kernel_launch(void* const* d_in, const int* in_sizes, int n_in,
                              void* d_out, int out_size) {
    const float* x     = (const float*)d_in[0];  // spike_seq [1024,16384,2]
    const float* w_exc = (const float*)d_in[1];  // [1,2]
    const float* w_inh = (const float*)d_in[2];  // scalar
    float* out = (float*)d_out;                  // [2,1024,16384]

    fmfm_kernel<<<(BATCH / TPB) * NCHUNK, TPB>>>((const float2*)x, w_exc, w_inh, out);
}